// round 13
// baseline (speedup 1.0000x reference)
#include <cuda_runtime.h>
#include <cuda_fp16.h>
#include <cstdint>

#define N_SPANS 1024
#define D 512
#define H 150
#define HP 160
#define WIN 250
#define OUTW (WIN + 1)
#define NT 256
#define TI 16            // spans per proj block

// byte strides
#define RA 144     // stage row stride: 72 halves (64 data + 8 pad)
#define RH 336     // h1 row stride: 168 halves (160 data + 8 pad)

// SMEM byte offsets (per-CTA total 89,344 B -> 2 CTAs/SM)
#define OF_H1  0         // 64*336  = 21504
#define OF_A0  21504     // 64*144  = 9216
#define OF_A1  30720
#define OF_B0  39936     // 160*144 = 23040
#define OF_B1  62976
#define OF_B2F 86016     // 160 f32
#define OF_W3F 86656     // 160 f32
#define OF_RED 87296     // 256 f32
#define OF_GIH 88320     // 512 halves (gi row, half)
#define SMEM_BYTES 89344

// ---------------- device scratch -------------------------------------------
__device__ __align__(16) float  d_Agi[N_SPANS * HP];
__device__ __align__(16) float  d_Agj[N_SPANS * HP];
__device__ __align__(16) __half d_B1h[HP * D];          // W1c^T [h][d]  (raw, shared)
__device__ __align__(16) __half d_B2h[HP * HP];         // W2^T  [h][k]
__device__ __align__(16) __half d_gh[N_SPANS * D];      // g in half

// ---------------- helpers ---------------------------------------------------
__device__ __forceinline__ uint32_t smem_u32(const void* p) {
    uint32_t a;
    asm("{ .reg .u64 t; cvta.to.shared.u64 t, %1; cvt.u32.u64 %0, t; }" : "=r"(a) : "l"(p));
    return a;
}
__device__ __forceinline__ void mma_f16(float* c, const uint32_t* a, const uint32_t* b) {
    asm volatile(
        "mma.sync.aligned.m16n8k16.row.col.f32.f16.f16.f32 "
        "{%0,%1,%2,%3}, {%4,%5,%6,%7}, {%8,%9}, {%0,%1,%2,%3};"
        : "+f"(c[0]), "+f"(c[1]), "+f"(c[2]), "+f"(c[3])
        : "r"(a[0]), "r"(a[1]), "r"(a[2]), "r"(a[3]), "r"(b[0]), "r"(b[1]));
}
__device__ __forceinline__ void ldm_x4(uint32_t* r, uint32_t saddr) {
    asm volatile("ldmatrix.sync.aligned.m8n8.x4.shared.b16 {%0,%1,%2,%3}, [%4];"
                 : "=r"(r[0]), "=r"(r[1]), "=r"(r[2]), "=r"(r[3]) : "r"(saddr));
}
__device__ __forceinline__ void ldm_x2(uint32_t* r, uint32_t saddr) {
    asm volatile("ldmatrix.sync.aligned.m8n8.x2.shared.b16 {%0,%1}, [%2];"
                 : "=r"(r[0]), "=r"(r[1]) : "r"(saddr));
}
#define CP16(dst, src)  asm volatile("cp.async.cg.shared.global [%0], [%1], 16;" :: "r"(dst), "l"(src))
#define CP_COMMIT()     asm volatile("cp.async.commit_group;" ::: "memory")
#define CP_WAIT0()      asm volatile("cp.async.wait_group 0;" ::: "memory")

__device__ __forceinline__ uint32_t pack2(float a, float b) {
    __half2 h = __floats2half2_rn(a, b);
    return *(uint32_t*)&h;
}
__device__ __forceinline__ uint4 hmul4(uint4 x, uint4 y) {
    uint4 r;
    *(__half2*)&r.x = __hmul2(*(__half2*)&x.x, *(__half2*)&y.x);
    *(__half2*)&r.y = __hmul2(*(__half2*)&x.y, *(__half2*)&y.y);
    *(__half2*)&r.z = __hmul2(*(__half2*)&x.z, *(__half2*)&y.z);
    *(__half2*)&r.w = __hmul2(*(__half2*)&x.w, *(__half2*)&y.w);
    return r;
}

// ---------------------------------------------------------------------------
// proj: Agi/Agj for TI spans per block; W1 elements reused TI times.
// ---------------------------------------------------------------------------
__global__ void __launch_bounds__(160) proj_kernel(const float* __restrict__ g,
                                                   const float* __restrict__ W1,
                                                   const float* __restrict__ b1) {
    __shared__ float gs[TI * D];                  // 32 KB
    const int i0 = blockIdx.x * TI;
    const int tid = threadIdx.x;

    for (int q = tid; q < TI * D / 4; q += 160)
        ((float4*)gs)[q] = ((const float4*)(g + i0 * D))[q];
    __syncthreads();

    const int h = (tid < H) ? tid : (H - 1);
    float a1[TI], a2[TI];
    const float b1v = b1[h];
#pragma unroll
    for (int s = 0; s < TI; s++) { a1[s] = b1v; a2[s] = 0.f; }

    const float* Wa = W1 + h;            // rows [0, D)
    const float* Wb = W1 + D * H + h;    // rows [D, 2D)
#pragma unroll 2
    for (int d = 0; d < D; d++) {
        const float wa = Wa[d * H];
        const float wb = Wb[d * H];
#pragma unroll
        for (int s = 0; s < TI; s++) {
            const float gv = gs[s * D + d];
            a1[s] = fmaf(gv, wa, a1[s]);
            a2[s] = fmaf(gv, wb, a2[s]);
        }
    }

    if (tid < HP) {
        const bool live = (tid < H);
#pragma unroll
        for (int s = 0; s < TI; s++) {
            d_Agi[(i0 + s) * HP + tid] = live ? a1[s] : 0.f;
            d_Agj[(i0 + s) * HP + tid] = live ? a2[s] : 0.f;
        }
    }
}

// fused: blocks [0,1024) convert g rows to half; blocks [1024,1184) build W1c^T/W2^T
__global__ void __launch_bounds__(512) prep_fused_kernel(const float* __restrict__ g,
                                                         const float* __restrict__ W1,
                                                         const float* __restrict__ W2) {
    const int b = blockIdx.x, tid = threadIdx.x;
    if (b < N_SPANS) {
        d_gh[b * D + tid] = __float2half_rn(g[b * D + tid]);
    } else {
        const int n = b - N_SPANS;          // 0..159
        const float v1 = (n < H) ? W1[(2 * D + tid) * H + n] : 0.f;
        d_B1h[n * D + tid] = __float2half_rn(v1);
        if (tid < HP) {
            const float v2 = (n < H && tid < H) ? W2[tid * H + n] : 0.f;
            d_B2h[n * HP + tid] = __float2half_rn(v2);
        }
    }
}

// ---------------------------------------------------------------------------
// Main fused kernel: CTA = (span i, window quarter). M=64, N=160, 8 warps 2x4.
// ---------------------------------------------------------------------------
__global__ void __launch_bounds__(NT, 2) pair_mma_kernel(const float* __restrict__ sm,
                                                         const float* __restrict__ W3,
                                                         const float* __restrict__ b2,
                                                         const float* __restrict__ b3,
                                                         float* __restrict__ out) {
    extern __shared__ char smc[];
    const uint32_t smb = smem_u32(smc);
    float* sB2 = (float*)(smc + OF_B2F);
    float* sW3 = (float*)(smc + OF_W3F);
    float* sRD = (float*)(smc + OF_RED);

    const int tid = threadIdx.x;
    const int lane = tid & 31;
    const int w = tid >> 5;
    const int gq = lane >> 2;
    const int tg = lane & 3;
    const int warp_m = w & 1;
    const int warp_n = w >> 1;

    const int i = blockIdx.x >> 2;
    const int quarter = blockIdx.x & 3;
    const int kbase = quarter * 64;

    if (i - WIN + kbase + 63 < 0) {
        if (tid < 64) out[i * OUTW + kbase + tid] = 0.f;
        return;
    }

    const int row_l = (lane & 7) + ((lane >> 3) & 1) * 8;
    const int col_l = (lane >> 4) * 16;
    const int rowB2l = lane & 7;
    const int colB2l = ((lane >> 3) & 1) * 16;
    const int OFA[2] = {OF_A0, OF_A1};
    const int OFB[2] = {OF_B0, OF_B1};

    const int am0 = tid >> 3, aseg0 = tid & 7;
    const int am1 = (tid + NT) >> 3, aseg1 = tid & 7;
    const int ajc0 = min(max(i - WIN + kbase + am0, 0), N_SPANS - 1);
    const int ajc1 = min(max(i - WIN + kbase + am1, 0), N_SPANS - 1);

    if (tid < 64) {
        *(uint4*)(smc + OF_GIH + tid * 16) = *(const uint4*)(d_gh + i * D + tid * 8);
    }
    for (int x = tid; x < HP; x += NT) {
        sB2[x] = (x < H) ? b2[x] : 0.f;
        sW3[x] = (x < H) ? W3[x] : 0.f;
    }
    __syncthreads();

    auto cp_B1 = [&](int ch, int buf) {
#pragma unroll
        for (int it = 0; it < 5; it++) {
            const int x = tid + it * NT;
            const int n = x >> 3, seg = x & 7;
            CP16(smb + OFB[buf] + n * RA + seg * 16,
                 (const char*)(d_B1h + n * D + ch * 64) + seg * 16);
        }
        CP_COMMIT();
    };
    auto ld_gj = [&](int ch, uint4* r) {
        r[0] = *(const uint4*)(d_gh + ajc0 * D + ch * 64 + aseg0 * 8);
        r[1] = *(const uint4*)(d_gh + ajc1 * D + ch * 64 + aseg1 * 8);
    };
    auto st_A = [&](int buf, int ch, const uint4* r) {
        const uint4 gi0 = *(const uint4*)(smc + OF_GIH + (ch * 64 + aseg0 * 8) * 2);
        *(uint4*)(smc + OFA[buf] + am0 * RA + aseg0 * 16) = hmul4(r[0], gi0);
        *(uint4*)(smc + OFA[buf] + am1 * RA + aseg1 * 16) = hmul4(r[1], gi0);
    };

    cp_B1(0, 0);
    {
        uint4 r0[2];
        ld_gj(0, r0);
        st_A(0, 0, r0);
    }

#pragma unroll
    for (int it = 0; it < 5; it++) {
        const int x = tid + it * NT;
        const int m = x / 20, grp = x % 20;
        const int jc = min(max(i - WIN + kbase + m, 0), N_SPANS - 1);
        const float4 ai0 = ((const float4*)(d_Agi + i * HP + grp * 8))[0];
        const float4 ai1 = ((const float4*)(d_Agi + i * HP + grp * 8))[1];
        const float4 aj0 = ((const float4*)(d_Agj + jc * HP + grp * 8))[0];
        const float4 aj1 = ((const float4*)(d_Agj + jc * HP + grp * 8))[1];
        uint4 o;
        o.x = pack2(ai0.x + aj0.x, ai0.y + aj0.y);
        o.y = pack2(ai0.z + aj0.z, ai0.w + aj0.w);
        o.z = pack2(ai1.x + aj1.x, ai1.y + aj1.y);
        o.w = pack2(ai1.z + aj1.z, ai1.w + aj1.w);
        *(uint4*)(smc + OF_H1 + m * RH + grp * 16) = o;
    }

    float acc[2][5][4];
#pragma unroll
    for (int ma = 0; ma < 2; ma++)
#pragma unroll
        for (int na = 0; na < 5; na++)
#pragma unroll
            for (int q = 0; q < 4; q++) acc[ma][na][q] = 0.f;

    auto mma_steps = [&](int abase, int bbase, int aks0, int nks, int astride) {
#pragma unroll 1
        for (int ks = 0; ks < nks; ks++) {
            uint32_t a[2][4];
#pragma unroll
            for (int ma = 0; ma < 2; ma++)
                ldm_x4(a[ma], smb + abase + (warp_m * 32 + ma * 16 + row_l) * astride + (aks0 + ks) * 32 + col_l);
            uint32_t b[5][2];
            {
                uint32_t t[4];
#pragma unroll
                for (int pr = 0; pr < 2; pr++) {
                    ldm_x4(t, smb + bbase + (warp_n * 40 + pr * 16 + row_l) * RA + ks * 32 + col_l);
                    b[pr * 2 + 0][0] = t[0]; b[pr * 2 + 0][1] = t[2];
                    b[pr * 2 + 1][0] = t[1]; b[pr * 2 + 1][1] = t[3];
                }
                ldm_x2(b[4], smb + bbase + (warp_n * 40 + 32 + rowB2l) * RA + ks * 32 + colB2l);
            }
#pragma unroll
            for (int ma = 0; ma < 2; ma++)
#pragma unroll
                for (int na = 0; na < 5; na++) mma_f16(acc[ma][na], a[ma], b[na]);
        }
    };

    auto cp_chunk2 = [&](int ch, int buf) {
        const int nseg = (ch == 2) ? 4 : 8;
        const int items = HP * nseg;
#pragma unroll
        for (int it = 0; it < 5; it++) {
            const int x = tid + it * NT;
            if (x < items) {
                const int n = x / nseg, seg = x % nseg;
                CP16(smb + OFB[buf] + n * RA + seg * 16,
                     (const char*)(d_B2h + n * HP + ch * 64) + seg * 16);
            }
        }
        CP_COMMIT();
    };

    // =================== GEMM1: 8 chunks, single-sync pipeline ==============
#pragma unroll 1
    for (int ch = 0; ch < 8; ch++) {
        const int cur = ch & 1;
        CP_WAIT0();
        __syncthreads();
        uint4 rgj[2];
        if (ch < 7) { ld_gj(ch + 1, rgj); cp_B1(ch + 1, cur ^ 1); }
        else        cp_chunk2(0, 0);
        mma_steps(OFA[cur], OFB[cur], 0, 4, RA);
        if (ch < 7) st_A(cur ^ 1, ch + 1, rgj);
    }

    // ====== Epilogue 1 =====================================================
#pragma unroll
    for (int ma = 0; ma < 2; ma++) {
        const int r0 = warp_m * 32 + ma * 16 + gq;
#pragma unroll
        for (int na = 0; na < 5; na++) {
            const int c0 = warp_n * 40 + na * 8 + tg * 2;
            uint32_t* p0 = (uint32_t*)(smc + OF_H1 + r0 * RH + c0 * 2);
            uint32_t* p1 = (uint32_t*)(smc + OF_H1 + (r0 + 8) * RH + c0 * 2);
            const float2 pre0 = __half22float2(*(__half2*)p0);
            const float2 pre1 = __half22float2(*(__half2*)p1);
            *p0 = pack2(fmaxf(acc[ma][na][0] + pre0.x, 0.f),
                        fmaxf(acc[ma][na][1] + pre0.y, 0.f));
            *p1 = pack2(fmaxf(acc[ma][na][2] + pre1.x, 0.f),
                        fmaxf(acc[ma][na][3] + pre1.y, 0.f));
        }
    }
#pragma unroll
    for (int ma = 0; ma < 2; ma++)
#pragma unroll
        for (int na = 0; na < 5; na++)
#pragma unroll
            for (int q = 0; q < 4; q++) acc[ma][na][q] = 0.f;

    CP_WAIT0();
    __syncthreads();

    // ========= GEMM2: 3 chunks (k64,k64,k32) ================================
#pragma unroll 1
    for (int ch = 0; ch < 3; ch++) {
        const int cur = ch & 1;
        if (ch < 2) cp_chunk2(ch + 1, cur ^ 1);
        mma_steps(OF_H1, OFB[cur], ch * 4, (ch < 2) ? 4 : 2, RH);
        if (ch < 2) { CP_WAIT0(); __syncthreads(); }
    }

    // ====== Epilogue 2 ======================================================
    float part[4] = {0.f, 0.f, 0.f, 0.f};
#pragma unroll
    for (int ma = 0; ma < 2; ma++) {
#pragma unroll
        for (int na = 0; na < 5; na++) {
            const int c0 = warp_n * 40 + na * 8 + tg * 2;
            const float2 bb = *(const float2*)(sB2 + c0);
            const float2 ww = *(const float2*)(sW3 + c0);
            part[ma * 2 + 0] += fmaxf(acc[ma][na][0] + bb.x, 0.f) * ww.x
                              + fmaxf(acc[ma][na][1] + bb.y, 0.f) * ww.y;
            part[ma * 2 + 1] += fmaxf(acc[ma][na][2] + bb.x, 0.f) * ww.x
                              + fmaxf(acc[ma][na][3] + bb.y, 0.f) * ww.y;
        }
    }
#pragma unroll
    for (int q = 0; q < 4; q++) {
        part[q] += __shfl_xor_sync(0xffffffffu, part[q], 1);
        part[q] += __shfl_xor_sync(0xffffffffu, part[q], 2);
    }
    if (tg == 0) {
        const int r0 = warp_m * 32 + gq;
        sRD[warp_n * 64 + r0 +  0] = part[0];
        sRD[warp_n * 64 + r0 +  8] = part[1];
        sRD[warp_n * 64 + r0 + 16] = part[2];
        sRD[warp_n * 64 + r0 + 24] = part[3];
    }
    __syncthreads();

    if (tid < 64) {
        const int m = tid;
        const int k = kbase + m;
        const float s = sRD[m] + sRD[64 + m] + sRD[128 + m] + sRD[192 + m] + b3[0];
        if (k < WIN) {
            const int j = i - WIN + k;
            out[i * OUTW + k] = (j >= 0) ? (sm[i] + sm[j] + s) : 0.f;
        } else if (k == WIN) {
            out[i * OUTW + WIN] = 0.f;
        }
    }
}

// ---------------------------------------------------------------------------
extern "C" void kernel_launch(void* const* d_in, const int* in_sizes, int n_in,
                              void* d_out, int out_size) {
    const float* g  = (const float*)d_in[0];
    const float* sm = (const float*)d_in[1];
    const float* W1 = (const float*)d_in[2];
    const float* b1 = (const float*)d_in[3];
    const float* W2 = (const float*)d_in[4];
    const float* b2 = (const float*)d_in[5];
    const float* W3 = (const float*)d_in[6];
    const float* b3 = (const float*)d_in[7];
    float* out = (float*)d_out;

    cudaFuncSetAttribute(pair_mma_kernel, cudaFuncAttributeMaxDynamicSharedMemorySize,
                         SMEM_BYTES);

    proj_kernel<<<N_SPANS / TI, 160>>>(g, W1, b1);
    prep_fused_kernel<<<N_SPANS + HP, 512>>>(g, W1, W2);
    pair_mma_kernel<<<4 * N_SPANS, NT, SMEM_BYTES>>>(sm, W3, b2, b3, out);
}

// round 14
// speedup vs baseline: 1.2061x; 1.2061x over previous
#include <cuda_runtime.h>
#include <cuda_fp16.h>
#include <cstdint>

#define N_SPANS 1024
#define D 512
#define H 150
#define HP 160
#define WIN 250
#define OUTW (WIN + 1)
#define NT 256
#define TI 8             // spans per proj_part block
#define DCH 128          // D-chunk per proj_part block
#define NDC (D / DCH)    // 4 D-chunks

// byte strides
#define RA 144     // stage row stride: 72 halves (64 data + 8 pad)
#define RH 336     // h1 row stride: 168 halves (160 data + 8 pad)

// SMEM byte offsets (per-CTA total 89,344 B -> 2 CTAs/SM)
#define OF_H1  0         // 64*336  = 21504
#define OF_A0  21504     // 64*144  = 9216
#define OF_A1  30720
#define OF_B0  39936     // 160*144 = 23040
#define OF_B1  62976
#define OF_B2F 86016     // 160 f32
#define OF_W3F 86656     // 160 f32
#define OF_RED 87296     // 256 f32
#define OF_GIH 88320     // 512 halves (gi row, half)
#define SMEM_BYTES 89344

// ---------------- device scratch -------------------------------------------
__device__ __align__(16) float  d_Agi[N_SPANS * HP];
__device__ __align__(16) float  d_Agj[N_SPANS * HP];
__device__ __align__(16) float  d_P1[NDC * N_SPANS * HP];   // proj partials (W1a)
__device__ __align__(16) float  d_P2[NDC * N_SPANS * HP];   // proj partials (W1b)
__device__ __align__(16) __half d_B1h[HP * D];          // W1c^T [h][d]
__device__ __align__(16) __half d_B2h[HP * HP];         // W2^T  [h][k]
__device__ __align__(16) __half d_gh[N_SPANS * D];      // g in half

// ---------------- helpers ---------------------------------------------------
__device__ __forceinline__ uint32_t smem_u32(const void* p) {
    uint32_t a;
    asm("{ .reg .u64 t; cvta.to.shared.u64 t, %1; cvt.u32.u64 %0, t; }" : "=r"(a) : "l"(p));
    return a;
}
__device__ __forceinline__ void mma_f16(float* c, const uint32_t* a, const uint32_t* b) {
    asm volatile(
        "mma.sync.aligned.m16n8k16.row.col.f32.f16.f16.f32 "
        "{%0,%1,%2,%3}, {%4,%5,%6,%7}, {%8,%9}, {%0,%1,%2,%3};"
        : "+f"(c[0]), "+f"(c[1]), "+f"(c[2]), "+f"(c[3])
        : "r"(a[0]), "r"(a[1]), "r"(a[2]), "r"(a[3]), "r"(b[0]), "r"(b[1]));
}
__device__ __forceinline__ void ldm_x4(uint32_t* r, uint32_t saddr) {
    asm volatile("ldmatrix.sync.aligned.m8n8.x4.shared.b16 {%0,%1,%2,%3}, [%4];"
                 : "=r"(r[0]), "=r"(r[1]), "=r"(r[2]), "=r"(r[3]) : "r"(saddr));
}
__device__ __forceinline__ void ldm_x2(uint32_t* r, uint32_t saddr) {
    asm volatile("ldmatrix.sync.aligned.m8n8.x2.shared.b16 {%0,%1}, [%2];"
                 : "=r"(r[0]), "=r"(r[1]) : "r"(saddr));
}
#define CP16(dst, src)  asm volatile("cp.async.cg.shared.global [%0], [%1], 16;" :: "r"(dst), "l"(src))
#define CP_COMMIT()     asm volatile("cp.async.commit_group;" ::: "memory")
#define CP_WAIT0()      asm volatile("cp.async.wait_group 0;" ::: "memory")

__device__ __forceinline__ uint32_t pack2(float a, float b) {
    __half2 h = __floats2half2_rn(a, b);
    return *(uint32_t*)&h;
}
__device__ __forceinline__ uint4 hmul4(uint4 x, uint4 y) {
    uint4 r;
    *(__half2*)&r.x = __hmul2(*(__half2*)&x.x, *(__half2*)&y.x);
    *(__half2*)&r.y = __hmul2(*(__half2*)&x.y, *(__half2*)&y.y);
    *(__half2*)&r.z = __hmul2(*(__half2*)&x.z, *(__half2*)&y.z);
    *(__half2*)&r.w = __hmul2(*(__half2*)&x.w, *(__half2*)&y.w);
    return r;
}

// ---------------------------------------------------------------------------
// proj stage 1: partial sums over a D-chunk for TI spans.
// grid = (N_SPANS/TI) * NDC blocks; W1 reuse = TI per element.
// ---------------------------------------------------------------------------
__global__ void __launch_bounds__(160) proj_part_kernel(const float* __restrict__ g,
                                                        const float* __restrict__ W1) {
    __shared__ float gs[TI * DCH];               // 4 KB
    const int si = blockIdx.x >> 2;              // span group
    const int dc = blockIdx.x & 3;               // D-chunk
    const int i0 = si * TI;
    const int tid = threadIdx.x;

    for (int q = tid; q < TI * DCH / 4; q += 160) {
        const int s = q >> 5, dq = q & 31;       // DCH/4 = 32
        ((float4*)gs)[q] = ((const float4*)(g + (i0 + s) * D + dc * DCH))[dq];
    }
    __syncthreads();

    const int h = (tid < H) ? tid : (H - 1);
    float a1[TI], a2[TI];
#pragma unroll
    for (int s = 0; s < TI; s++) { a1[s] = 0.f; a2[s] = 0.f; }

    const float* Wa = W1 + (dc * DCH) * H + h;
    const float* Wb = W1 + (D + dc * DCH) * H + h;
#pragma unroll 4
    for (int d = 0; d < DCH; d++) {
        const float wa = Wa[d * H];
        const float wb = Wb[d * H];
#pragma unroll
        for (int s = 0; s < TI; s++) {
            const float gv = gs[s * DCH + d];
            a1[s] = fmaf(gv, wa, a1[s]);
            a2[s] = fmaf(gv, wb, a2[s]);
        }
    }

    if (tid < HP) {
        float* p1 = d_P1 + dc * (N_SPANS * HP);
        float* p2 = d_P2 + dc * (N_SPANS * HP);
#pragma unroll
        for (int s = 0; s < TI; s++) {
            p1[(i0 + s) * HP + tid] = a1[s];
            p2[(i0 + s) * HP + tid] = a2[s];
        }
    }
}

// proj stage 2: Agi = b1 + sum_dc P1; Agj = sum_dc P2 (fixed order, deterministic)
__global__ void __launch_bounds__(160) proj_reduce_kernel(const float* __restrict__ b1) {
    const int i = blockIdx.x, h = threadIdx.x;
    float v1 = 0.f, v2 = 0.f;
    if (h < H) {
        v1 = b1[h];
#pragma unroll
        for (int dc = 0; dc < NDC; dc++) {
            v1 += d_P1[dc * (N_SPANS * HP) + i * HP + h];
            v2 += d_P2[dc * (N_SPANS * HP) + i * HP + h];
        }
    }
    d_Agi[i * HP + h] = v1;
    d_Agj[i * HP + h] = v2;
}

// fused: blocks [0,1024) convert g rows to half; blocks [1024,1184) build W1c^T/W2^T
__global__ void __launch_bounds__(512) prep_fused_kernel(const float* __restrict__ g,
                                                         const float* __restrict__ W1,
                                                         const float* __restrict__ W2) {
    const int b = blockIdx.x, tid = threadIdx.x;
    if (b < N_SPANS) {
        d_gh[b * D + tid] = __float2half_rn(g[b * D + tid]);
    } else {
        const int n = b - N_SPANS;          // 0..159
        const float v1 = (n < H) ? W1[(2 * D + tid) * H + n] : 0.f;
        d_B1h[n * D + tid] = __float2half_rn(v1);
        if (tid < HP) {
            const float v2 = (n < H && tid < H) ? W2[tid * H + n] : 0.f;
            d_B2h[n * HP + tid] = __float2half_rn(v2);
        }
    }
}

// ---------------------------------------------------------------------------
// Main fused kernel: CTA = (span i, window quarter). M=64, N=160, 8 warps 2x4.
// ---------------------------------------------------------------------------
__global__ void __launch_bounds__(NT, 2) pair_mma_kernel(const float* __restrict__ sm,
                                                         const float* __restrict__ W3,
                                                         const float* __restrict__ b2,
                                                         const float* __restrict__ b3,
                                                         float* __restrict__ out) {
    extern __shared__ char smc[];
    const uint32_t smb = smem_u32(smc);
    float* sB2 = (float*)(smc + OF_B2F);
    float* sW3 = (float*)(smc + OF_W3F);
    float* sRD = (float*)(smc + OF_RED);

    const int tid = threadIdx.x;
    const int lane = tid & 31;
    const int w = tid >> 5;
    const int gq = lane >> 2;
    const int tg = lane & 3;
    const int warp_m = w & 1;
    const int warp_n = w >> 1;

    const int i = blockIdx.x >> 2;
    const int quarter = blockIdx.x & 3;
    const int kbase = quarter * 64;

    if (i - WIN + kbase + 63 < 0) {
        if (tid < 64) out[i * OUTW + kbase + tid] = 0.f;
        return;
    }

    const int row_l = (lane & 7) + ((lane >> 3) & 1) * 8;
    const int col_l = (lane >> 4) * 16;
    const int rowB2l = lane & 7;
    const int colB2l = ((lane >> 3) & 1) * 16;
    const int OFA[2] = {OF_A0, OF_A1};
    const int OFB[2] = {OF_B0, OF_B1};

    const int am0 = tid >> 3, aseg0 = tid & 7;
    const int am1 = (tid + NT) >> 3, aseg1 = tid & 7;
    const int ajc0 = min(max(i - WIN + kbase + am0, 0), N_SPANS - 1);
    const int ajc1 = min(max(i - WIN + kbase + am1, 0), N_SPANS - 1);

    if (tid < 64) {
        *(uint4*)(smc + OF_GIH + tid * 16) = *(const uint4*)(d_gh + i * D + tid * 8);
    }
    for (int x = tid; x < HP; x += NT) {
        sB2[x] = (x < H) ? b2[x] : 0.f;
        sW3[x] = (x < H) ? W3[x] : 0.f;
    }
    __syncthreads();

    auto cp_B1 = [&](int ch, int buf) {
#pragma unroll
        for (int it = 0; it < 5; it++) {
            const int x = tid + it * NT;
            const int n = x >> 3, seg = x & 7;
            CP16(smb + OFB[buf] + n * RA + seg * 16,
                 (const char*)(d_B1h + n * D + ch * 64) + seg * 16);
        }
        CP_COMMIT();
    };
    auto ld_gj = [&](int ch, uint4* r) {
        r[0] = *(const uint4*)(d_gh + ajc0 * D + ch * 64 + aseg0 * 8);
        r[1] = *(const uint4*)(d_gh + ajc1 * D + ch * 64 + aseg1 * 8);
    };
    auto st_A = [&](int buf, int ch, const uint4* r) {
        const uint4 gi0 = *(const uint4*)(smc + OF_GIH + (ch * 64 + aseg0 * 8) * 2);
        *(uint4*)(smc + OFA[buf] + am0 * RA + aseg0 * 16) = hmul4(r[0], gi0);
        *(uint4*)(smc + OFA[buf] + am1 * RA + aseg1 * 16) = hmul4(r[1], gi0);
    };

    cp_B1(0, 0);
    {
        uint4 r0[2];
        ld_gj(0, r0);
        st_A(0, 0, r0);
    }

#pragma unroll
    for (int it = 0; it < 5; it++) {
        const int x = tid + it * NT;
        const int m = x / 20, grp = x % 20;
        const int jc = min(max(i - WIN + kbase + m, 0), N_SPANS - 1);
        const float4 ai0 = ((const float4*)(d_Agi + i * HP + grp * 8))[0];
        const float4 ai1 = ((const float4*)(d_Agi + i * HP + grp * 8))[1];
        const float4 aj0 = ((const float4*)(d_Agj + jc * HP + grp * 8))[0];
        const float4 aj1 = ((const float4*)(d_Agj + jc * HP + grp * 8))[1];
        uint4 o;
        o.x = pack2(ai0.x + aj0.x, ai0.y + aj0.y);
        o.y = pack2(ai0.z + aj0.z, ai0.w + aj0.w);
        o.z = pack2(ai1.x + aj1.x, ai1.y + aj1.y);
        o.w = pack2(ai1.z + aj1.z, ai1.w + aj1.w);
        *(uint4*)(smc + OF_H1 + m * RH + grp * 16) = o;
    }

    float acc[2][5][4];
#pragma unroll
    for (int ma = 0; ma < 2; ma++)
#pragma unroll
        for (int na = 0; na < 5; na++)
#pragma unroll
            for (int q = 0; q < 4; q++) acc[ma][na][q] = 0.f;

    auto mma_steps = [&](int abase, int bbase, int aks0, int nks, int astride) {
#pragma unroll 1
        for (int ks = 0; ks < nks; ks++) {
            uint32_t a[2][4];
#pragma unroll
            for (int ma = 0; ma < 2; ma++)
                ldm_x4(a[ma], smb + abase + (warp_m * 32 + ma * 16 + row_l) * astride + (aks0 + ks) * 32 + col_l);
            uint32_t b[5][2];
            {
                uint32_t t[4];
#pragma unroll
                for (int pr = 0; pr < 2; pr++) {
                    ldm_x4(t, smb + bbase + (warp_n * 40 + pr * 16 + row_l) * RA + ks * 32 + col_l);
                    b[pr * 2 + 0][0] = t[0]; b[pr * 2 + 0][1] = t[2];
                    b[pr * 2 + 1][0] = t[1]; b[pr * 2 + 1][1] = t[3];
                }
                ldm_x2(b[4], smb + bbase + (warp_n * 40 + 32 + rowB2l) * RA + ks * 32 + colB2l);
            }
#pragma unroll
            for (int ma = 0; ma < 2; ma++)
#pragma unroll
                for (int na = 0; na < 5; na++) mma_f16(acc[ma][na], a[ma], b[na]);
        }
    };

    auto cp_chunk2 = [&](int ch, int buf) {
        const int nseg = (ch == 2) ? 4 : 8;
        const int items = HP * nseg;
#pragma unroll
        for (int it = 0; it < 5; it++) {
            const int x = tid + it * NT;
            if (x < items) {
                const int n = x / nseg, seg = x % nseg;
                CP16(smb + OFB[buf] + n * RA + seg * 16,
                     (const char*)(d_B2h + n * HP + ch * 64) + seg * 16);
            }
        }
        CP_COMMIT();
    };

    // =================== GEMM1: 8 chunks, single-sync pipeline ==============
#pragma unroll 1
    for (int ch = 0; ch < 8; ch++) {
        const int cur = ch & 1;
        CP_WAIT0();
        __syncthreads();
        uint4 rgj[2];
        if (ch < 7) { ld_gj(ch + 1, rgj); cp_B1(ch + 1, cur ^ 1); }
        else        cp_chunk2(0, 0);
        mma_steps(OFA[cur], OFB[cur], 0, 4, RA);
        if (ch < 7) st_A(cur ^ 1, ch + 1, rgj);
    }

    // ====== Epilogue 1 =====================================================
#pragma unroll
    for (int ma = 0; ma < 2; ma++) {
        const int r0 = warp_m * 32 + ma * 16 + gq;
#pragma unroll
        for (int na = 0; na < 5; na++) {
            const int c0 = warp_n * 40 + na * 8 + tg * 2;
            uint32_t* p0 = (uint32_t*)(smc + OF_H1 + r0 * RH + c0 * 2);
            uint32_t* p1 = (uint32_t*)(smc + OF_H1 + (r0 + 8) * RH + c0 * 2);
            const float2 pre0 = __half22float2(*(__half2*)p0);
            const float2 pre1 = __half22float2(*(__half2*)p1);
            *p0 = pack2(fmaxf(acc[ma][na][0] + pre0.x, 0.f),
                        fmaxf(acc[ma][na][1] + pre0.y, 0.f));
            *p1 = pack2(fmaxf(acc[ma][na][2] + pre1.x, 0.f),
                        fmaxf(acc[ma][na][3] + pre1.y, 0.f));
        }
    }
#pragma unroll
    for (int ma = 0; ma < 2; ma++)
#pragma unroll
        for (int na = 0; na < 5; na++)
#pragma unroll
            for (int q = 0; q < 4; q++) acc[ma][na][q] = 0.f;

    CP_WAIT0();
    __syncthreads();

    // ========= GEMM2: 3 chunks (k64,k64,k32) ================================
#pragma unroll 1
    for (int ch = 0; ch < 3; ch++) {
        const int cur = ch & 1;
        if (ch < 2) cp_chunk2(ch + 1, cur ^ 1);
        mma_steps(OF_H1, OFB[cur], ch * 4, (ch < 2) ? 4 : 2, RH);
        if (ch < 2) { CP_WAIT0(); __syncthreads(); }
    }

    // ====== Epilogue 2 ======================================================
    float part[4] = {0.f, 0.f, 0.f, 0.f};
#pragma unroll
    for (int ma = 0; ma < 2; ma++) {
#pragma unroll
        for (int na = 0; na < 5; na++) {
            const int c0 = warp_n * 40 + na * 8 + tg * 2;
            const float2 bb = *(const float2*)(sB2 + c0);
            const float2 ww = *(const float2*)(sW3 + c0);
            part[ma * 2 + 0] += fmaxf(acc[ma][na][0] + bb.x, 0.f) * ww.x
                              + fmaxf(acc[ma][na][1] + bb.y, 0.f) * ww.y;
            part[ma * 2 + 1] += fmaxf(acc[ma][na][2] + bb.x, 0.f) * ww.x
                              + fmaxf(acc[ma][na][3] + bb.y, 0.f) * ww.y;
        }
    }
#pragma unroll
    for (int q = 0; q < 4; q++) {
        part[q] += __shfl_xor_sync(0xffffffffu, part[q], 1);
        part[q] += __shfl_xor_sync(0xffffffffu, part[q], 2);
    }
    if (tg == 0) {
        const int r0 = warp_m * 32 + gq;
        sRD[warp_n * 64 + r0 +  0] = part[0];
        sRD[warp_n * 64 + r0 +  8] = part[1];
        sRD[warp_n * 64 + r0 + 16] = part[2];
        sRD[warp_n * 64 + r0 + 24] = part[3];
    }
    __syncthreads();

    if (tid < 64) {
        const int m = tid;
        const int k = kbase + m;
        const float s = sRD[m] + sRD[64 + m] + sRD[128 + m] + sRD[192 + m] + b3[0];
        if (k < WIN) {
            const int j = i - WIN + k;
            out[i * OUTW + k] = (j >= 0) ? (sm[i] + sm[j] + s) : 0.f;
        } else if (k == WIN) {
            out[i * OUTW + WIN] = 0.f;
        }
    }
}

// ---------------------------------------------------------------------------
extern "C" void kernel_launch(void* const* d_in, const int* in_sizes, int n_in,
                              void* d_out, int out_size) {
    const float* g  = (const float*)d_in[0];
    const float* sm = (const float*)d_in[1];
    const float* W1 = (const float*)d_in[2];
    const float* b1 = (const float*)d_in[3];
    const float* W2 = (const float*)d_in[4];
    const float* b2 = (const float*)d_in[5];
    const float* W3 = (const float*)d_in[6];
    const float* b3 = (const float*)d_in[7];
    float* out = (float*)d_out;

    cudaFuncSetAttribute(pair_mma_kernel, cudaFuncAttributeMaxDynamicSharedMemorySize,
                         SMEM_BYTES);

    proj_part_kernel<<<(N_SPANS / TI) * NDC, 160>>>(g, W1);
    prep_fused_kernel<<<N_SPANS + HP, 512>>>(g, W1, W2);
    proj_reduce_kernel<<<N_SPANS, 160>>>(b1);
    pair_mma_kernel<<<4 * N_SPANS, NT, SMEM_BYTES>>>(sm, W3, b2, b3, out);
}

// round 15
// speedup vs baseline: 1.4108x; 1.1697x over previous
#include <cuda_runtime.h>
#include <cuda_fp16.h>
#include <cstdint>

#define N_SPANS 1024
#define D 512
#define H 150
#define HP 160
#define WIN 250
#define OUTW (WIN + 1)
#define NT 256
#define TI 8             // spans per proj_part block
#define DCH 128          // D-chunk per proj_part block
#define NDC (D / DCH)    // 4 D-chunks

// byte strides
#define RA 144     // stage row stride: 72 halves (64 data + 8 pad)
#define RH 336     // h1 row stride: 168 halves (160 data + 8 pad)

// SMEM byte offsets (per-CTA total 89,344 B -> 2 CTAs/SM)
#define OF_H1  0         // 64*336  = 21504
#define OF_A0  21504     // 64*144  = 9216
#define OF_A1  30720
#define OF_B0  39936     // 160*144 = 23040
#define OF_B1  62976
#define OF_B2F 86016     // 160 f32
#define OF_W3F 86656     // 160 f32
#define OF_RED 87296     // 256 f32
#define OF_GIH 88320     // 512 halves (gi row, half)
#define SMEM_BYTES 89344

// ---------------- device scratch -------------------------------------------
__device__ __align__(16) float  d_Agi[N_SPANS * HP];
__device__ __align__(16) float  d_Agj[N_SPANS * HP];
__device__ __align__(16) float  d_P1[NDC * N_SPANS * HP];
__device__ __align__(16) float  d_P2[NDC * N_SPANS * HP];
__device__ __align__(16) __half d_B1h[HP * D];
__device__ __align__(16) __half d_B2h[HP * HP];
__device__ __align__(16) __half d_gh[N_SPANS * D];

// ---------------- helpers ---------------------------------------------------
__device__ __forceinline__ uint32_t smem_u32(const void* p) {
    uint32_t a;
    asm("{ .reg .u64 t; cvta.to.shared.u64 t, %1; cvt.u32.u64 %0, t; }" : "=r"(a) : "l"(p));
    return a;
}
__device__ __forceinline__ void mma_f16(float* c, const uint32_t* a, const uint32_t* b) {
    asm volatile(
        "mma.sync.aligned.m16n8k16.row.col.f32.f16.f16.f32 "
        "{%0,%1,%2,%3}, {%4,%5,%6,%7}, {%8,%9}, {%0,%1,%2,%3};"
        : "+f"(c[0]), "+f"(c[1]), "+f"(c[2]), "+f"(c[3])
        : "r"(a[0]), "r"(a[1]), "r"(a[2]), "r"(a[3]), "r"(b[0]), "r"(b[1]));
}
__device__ __forceinline__ void ldm_x4(uint32_t* r, uint32_t saddr) {
    asm volatile("ldmatrix.sync.aligned.m8n8.x4.shared.b16 {%0,%1,%2,%3}, [%4];"
                 : "=r"(r[0]), "=r"(r[1]), "=r"(r[2]), "=r"(r[3]) : "r"(saddr));
}
__device__ __forceinline__ void ldm_x2(uint32_t* r, uint32_t saddr) {
    asm volatile("ldmatrix.sync.aligned.m8n8.x2.shared.b16 {%0,%1}, [%2];"
                 : "=r"(r[0]), "=r"(r[1]) : "r"(saddr));
}
#define CP16(dst, src)  asm volatile("cp.async.cg.shared.global [%0], [%1], 16;" :: "r"(dst), "l"(src))
#define CP_COMMIT()     asm volatile("cp.async.commit_group;" ::: "memory")
#define CP_WAIT0()      asm volatile("cp.async.wait_group 0;" ::: "memory")

__device__ __forceinline__ uint32_t pack2(float a, float b) {
    __half2 h = __floats2half2_rn(a, b);
    return *(uint32_t*)&h;
}
__device__ __forceinline__ uint4 hmul4(uint4 x, uint4 y) {
    uint4 r;
    *(__half2*)&r.x = __hmul2(*(__half2*)&x.x, *(__half2*)&y.x);
    *(__half2*)&r.y = __hmul2(*(__half2*)&x.y, *(__half2*)&y.y);
    *(__half2*)&r.z = __hmul2(*(__half2*)&x.z, *(__half2*)&y.z);
    *(__half2*)&r.w = __hmul2(*(__half2*)&x.w, *(__half2*)&y.w);
    return r;
}

// One k-chunk of MMAs: all addresses are base + compile-time immediates.
template<int ASTRIDE, int NKS>
__device__ __forceinline__ void mma_chunk(uint32_t aaddr, uint32_t b0a, uint32_t b1a,
                                          uint32_t b2a, float acc[2][5][4]) {
#pragma unroll
    for (int ks = 0; ks < NKS; ks++) {
        uint32_t a0[4], a1[4], t0[4], t1[4], b4[2];
        ldm_x4(a0, aaddr + ks * 32);
        ldm_x4(a1, aaddr + 16 * ASTRIDE + ks * 32);
        ldm_x4(t0, b0a + ks * 32);
        ldm_x4(t1, b1a + ks * 32);
        ldm_x2(b4, b2a + ks * 32);
        uint32_t b0[2] = {t0[0], t0[2]}, b1[2] = {t0[1], t0[3]};
        uint32_t b2[2] = {t1[0], t1[2]}, b3[2] = {t1[1], t1[3]};
        mma_f16(acc[0][0], a0, b0); mma_f16(acc[0][1], a0, b1);
        mma_f16(acc[0][2], a0, b2); mma_f16(acc[0][3], a0, b3);
        mma_f16(acc[0][4], a0, b4);
        mma_f16(acc[1][0], a1, b0); mma_f16(acc[1][1], a1, b1);
        mma_f16(acc[1][2], a1, b2); mma_f16(acc[1][3], a1, b3);
        mma_f16(acc[1][4], a1, b4);
    }
}

// ---------------------------------------------------------------------------
// proj stage 1 + 2 (unchanged from R14)
// ---------------------------------------------------------------------------
__global__ void __launch_bounds__(160) proj_part_kernel(const float* __restrict__ g,
                                                        const float* __restrict__ W1) {
    __shared__ float gs[TI * DCH];
    const int si = blockIdx.x >> 2;
    const int dc = blockIdx.x & 3;
    const int i0 = si * TI;
    const int tid = threadIdx.x;

    for (int q = tid; q < TI * DCH / 4; q += 160) {
        const int s = q >> 5, dq = q & 31;
        ((float4*)gs)[q] = ((const float4*)(g + (i0 + s) * D + dc * DCH))[dq];
    }
    __syncthreads();

    const int h = (tid < H) ? tid : (H - 1);
    float a1[TI], a2[TI];
#pragma unroll
    for (int s = 0; s < TI; s++) { a1[s] = 0.f; a2[s] = 0.f; }

    const float* Wa = W1 + (dc * DCH) * H + h;
    const float* Wb = W1 + (D + dc * DCH) * H + h;
#pragma unroll 4
    for (int d = 0; d < DCH; d++) {
        const float wa = Wa[d * H];
        const float wb = Wb[d * H];
#pragma unroll
        for (int s = 0; s < TI; s++) {
            const float gv = gs[s * DCH + d];
            a1[s] = fmaf(gv, wa, a1[s]);
            a2[s] = fmaf(gv, wb, a2[s]);
        }
    }

    if (tid < HP) {
        float* p1 = d_P1 + dc * (N_SPANS * HP);
        float* p2 = d_P2 + dc * (N_SPANS * HP);
#pragma unroll
        for (int s = 0; s < TI; s++) {
            p1[(i0 + s) * HP + tid] = a1[s];
            p2[(i0 + s) * HP + tid] = a2[s];
        }
    }
}

__global__ void __launch_bounds__(160) proj_reduce_kernel(const float* __restrict__ b1) {
    const int i = blockIdx.x, h = threadIdx.x;
    float v1 = 0.f, v2 = 0.f;
    if (h < H) {
        v1 = b1[h];
#pragma unroll
        for (int dc = 0; dc < NDC; dc++) {
            v1 += d_P1[dc * (N_SPANS * HP) + i * HP + h];
            v2 += d_P2[dc * (N_SPANS * HP) + i * HP + h];
        }
    }
    d_Agi[i * HP + h] = v1;
    d_Agj[i * HP + h] = v2;
}

__global__ void __launch_bounds__(512) prep_fused_kernel(const float* __restrict__ g,
                                                         const float* __restrict__ W1,
                                                         const float* __restrict__ W2) {
    const int b = blockIdx.x, tid = threadIdx.x;
    if (b < N_SPANS) {
        d_gh[b * D + tid] = __float2half_rn(g[b * D + tid]);
    } else {
        const int n = b - N_SPANS;
        const float v1 = (n < H) ? W1[(2 * D + tid) * H + n] : 0.f;
        d_B1h[n * D + tid] = __float2half_rn(v1);
        if (tid < HP) {
            const float v2 = (n < H && tid < H) ? W2[tid * H + n] : 0.f;
            d_B2h[n * HP + tid] = __float2half_rn(v2);
        }
    }
}

// ---------------------------------------------------------------------------
// Main fused kernel
// ---------------------------------------------------------------------------
__global__ void __launch_bounds__(NT, 2) pair_mma_kernel(const float* __restrict__ sm,
                                                         const float* __restrict__ W3,
                                                         const float* __restrict__ b2,
                                                         const float* __restrict__ b3,
                                                         float* __restrict__ out) {
    extern __shared__ char smc[];
    const uint32_t smb = smem_u32(smc);
    float* sB2 = (float*)(smc + OF_B2F);
    float* sW3 = (float*)(smc + OF_W3F);
    float* sRD = (float*)(smc + OF_RED);

    const int tid = threadIdx.x;
    const int lane = tid & 31;
    const int w = tid >> 5;
    const int gq = lane >> 2;
    const int tg = lane & 3;
    const int warp_m = w & 1;
    const int warp_n = w >> 1;

    const int i = blockIdx.x >> 2;
    const int quarter = blockIdx.x & 3;
    const int kbase = quarter * 64;

    if (i - WIN + kbase + 63 < 0) {
        if (tid < 64) out[i * OUTW + kbase + tid] = 0.f;
        return;
    }

    const int row_l = (lane & 7) + ((lane >> 3) & 1) * 8;
    const int col_l = (lane >> 4) * 16;
    const int rowB2l = lane & 7;
    const int colB2l = ((lane >> 3) & 1) * 16;

    // precomputed ldmatrix lane offsets (bytes from tile base)
    const uint32_t offA_RA = (warp_m * 32 + row_l) * RA + col_l;
    const uint32_t offA_RH = (warp_m * 32 + row_l) * RH + col_l;
    const uint32_t offB_p0 = (warp_n * 40 + row_l) * RA + col_l;
    const uint32_t offB_p1 = (warp_n * 40 + 16 + row_l) * RA + col_l;
    const uint32_t offB_x2 = (warp_n * 40 + 32 + rowB2l) * RA + colB2l;

    const uint32_t bufA[2] = {smb + OF_A0, smb + OF_A1};
    const uint32_t bufB[2] = {smb + OF_B0, smb + OF_B1};

    // precomputed cp.async offsets (5 B-items, 2 A-items per thread)
    uint32_t dstB[5], srcB[5];
#pragma unroll
    for (int it = 0; it < 5; it++) {
        const int x = tid + it * NT;
        const int n = x >> 3, seg = x & 7;
        dstB[it] = n * RA + seg * 16;
        srcB[it] = n * (D * 2) + seg * 16;   // bytes into d_B1h row-major
    }
    const int am0 = tid >> 3, aseg = tid & 7;
    const int am1 = (tid + NT) >> 3;
    const int ajc0 = min(max(i - WIN + kbase + am0, 0), N_SPANS - 1);
    const int ajc1 = min(max(i - WIN + kbase + am1, 0), N_SPANS - 1);
    const char* pgj0 = (const char*)(d_gh + ajc0 * D) + aseg * 16;
    const char* pgj1 = (const char*)(d_gh + ajc1 * D) + aseg * 16;
    const uint32_t dstA0 = am0 * RA + aseg * 16;
    const uint32_t dstA1 = am1 * RA + aseg * 16;
    const uint32_t gihA = smb + OF_GIH + aseg * 16;   // + ch*128

    if (tid < 64) {
        *(uint4*)(smc + OF_GIH + tid * 16) = *(const uint4*)(d_gh + i * D + tid * 8);
    }
    for (int x = tid; x < HP; x += NT) {
        sB2[x] = (x < H) ? b2[x] : 0.f;
        sW3[x] = (x < H) ? W3[x] : 0.f;
    }
    __syncthreads();

    auto cp_B1 = [&](int ch, int buf) {
#pragma unroll
        for (int it = 0; it < 5; it++)
            CP16(bufB[buf] + dstB[it], (const char*)d_B1h + srcB[it] + ch * 128);
        CP_COMMIT();
    };
    auto ld_gj = [&](int ch, uint4* r) {
        r[0] = *(const uint4*)(pgj0 + ch * 128);
        r[1] = *(const uint4*)(pgj1 + ch * 128);
    };
    auto st_A = [&](int buf, int ch, const uint4* r) {
        const uint4 gi0 = *(const uint4*)(smc + (gihA - smb) + ch * 128);
        *(uint4*)(smc + (bufA[buf] - smb) + dstA0) = hmul4(r[0], gi0);
        *(uint4*)(smc + (bufA[buf] - smb) + dstA1) = hmul4(r[1], gi0);
    };
    auto cp_chunk2 = [&](int ch, int buf) {
        const int nseg = (ch == 2) ? 4 : 8;
        const int items = HP * nseg;
#pragma unroll
        for (int it = 0; it < 5; it++) {
            const int x = tid + it * NT;
            if (x < items) {
                const int n = x / nseg, seg = x % nseg;
                CP16(bufB[buf] + n * RA + seg * 16,
                     (const char*)(d_B2h + n * HP + ch * 64) + seg * 16);
            }
        }
        CP_COMMIT();
    };

    cp_B1(0, 0);
    {
        uint4 r0[2];
        ld_gj(0, r0);
        st_A(0, 0, r0);
    }

#pragma unroll
    for (int it = 0; it < 5; it++) {
        const int x = tid + it * NT;
        const int m = x / 20, grp = x % 20;
        const int jc = min(max(i - WIN + kbase + m, 0), N_SPANS - 1);
        const float4 ai0 = ((const float4*)(d_Agi + i * HP + grp * 8))[0];
        const float4 ai1 = ((const float4*)(d_Agi + i * HP + grp * 8))[1];
        const float4 aj0 = ((const float4*)(d_Agj + jc * HP + grp * 8))[0];
        const float4 aj1 = ((const float4*)(d_Agj + jc * HP + grp * 8))[1];
        uint4 o;
        o.x = pack2(ai0.x + aj0.x, ai0.y + aj0.y);
        o.y = pack2(ai0.z + aj0.z, ai0.w + aj0.w);
        o.z = pack2(ai1.x + aj1.x, ai1.y + aj1.y);
        o.w = pack2(ai1.z + aj1.z, ai1.w + aj1.w);
        *(uint4*)(smc + OF_H1 + m * RH + grp * 16) = o;
    }

    float acc[2][5][4];
#pragma unroll
    for (int ma = 0; ma < 2; ma++)
#pragma unroll
        for (int na = 0; na < 5; na++)
#pragma unroll
            for (int q = 0; q < 4; q++) acc[ma][na][q] = 0.f;

    // =================== GEMM1: 8 chunks, fully unrolled ====================
#pragma unroll
    for (int ch = 0; ch < 8; ch++) {
        const int cur = ch & 1;
        CP_WAIT0();
        __syncthreads();
        uint4 rgj[2];
        if (ch < 7) { ld_gj(ch + 1, rgj); cp_B1(ch + 1, cur ^ 1); }
        else        cp_chunk2(0, 0);
        mma_chunk<RA, 4>(bufA[cur] + offA_RA, bufB[cur] + offB_p0,
                         bufB[cur] + offB_p1, bufB[cur] + offB_x2, acc);
        if (ch < 7) st_A(cur ^ 1, ch + 1, rgj);
    }

    // ====== Epilogue 1 ======================================================
#pragma unroll
    for (int ma = 0; ma < 2; ma++) {
        const int r0 = warp_m * 32 + ma * 16 + gq;
#pragma unroll
        for (int na = 0; na < 5; na++) {
            const int c0 = warp_n * 40 + na * 8 + tg * 2;
            uint32_t* p0 = (uint32_t*)(smc + OF_H1 + r0 * RH + c0 * 2);
            uint32_t* p1 = (uint32_t*)(smc + OF_H1 + (r0 + 8) * RH + c0 * 2);
            const float2 pre0 = __half22float2(*(__half2*)p0);
            const float2 pre1 = __half22float2(*(__half2*)p1);
            *p0 = pack2(fmaxf(acc[ma][na][0] + pre0.x, 0.f),
                        fmaxf(acc[ma][na][1] + pre0.y, 0.f));
            *p1 = pack2(fmaxf(acc[ma][na][2] + pre1.x, 0.f),
                        fmaxf(acc[ma][na][3] + pre1.y, 0.f));
        }
    }
#pragma unroll
    for (int ma = 0; ma < 2; ma++)
#pragma unroll
        for (int na = 0; na < 5; na++)
#pragma unroll
            for (int q = 0; q < 4; q++) acc[ma][na][q] = 0.f;

    CP_WAIT0();
    __syncthreads();

    // ========= GEMM2: 3 chunks (k64,k64,k32), unrolled ======================
    const uint32_t aH1 = smb + OF_H1 + offA_RH;
#pragma unroll
    for (int ch = 0; ch < 3; ch++) {
        const int cur = ch & 1;
        if (ch < 2) cp_chunk2(ch + 1, cur ^ 1);
        if (ch < 2)
            mma_chunk<RH, 4>(aH1 + ch * 128, bufB[cur] + offB_p0,
                             bufB[cur] + offB_p1, bufB[cur] + offB_x2, acc);
        else
            mma_chunk<RH, 2>(aH1 + ch * 128, bufB[cur] + offB_p0,
                             bufB[cur] + offB_p1, bufB[cur] + offB_x2, acc);
        if (ch < 2) { CP_WAIT0(); __syncthreads(); }
    }

    // ====== Epilogue 2 ======================================================
    float part[4] = {0.f, 0.f, 0.f, 0.f};
#pragma unroll
    for (int ma = 0; ma < 2; ma++) {
#pragma unroll
        for (int na = 0; na < 5; na++) {
            const int c0 = warp_n * 40 + na * 8 + tg * 2;
            const float2 bb = *(const float2*)(sB2 + c0);
            const float2 ww = *(const float2*)(sW3 + c0);
            part[ma * 2 + 0] += fmaxf(acc[ma][na][0] + bb.x, 0.f) * ww.x
                              + fmaxf(acc[ma][na][1] + bb.y, 0.f) * ww.y;
            part[ma * 2 + 1] += fmaxf(acc[ma][na][2] + bb.x, 0.f) * ww.x
                              + fmaxf(acc[ma][na][3] + bb.y, 0.f) * ww.y;
        }
    }
#pragma unroll
    for (int q = 0; q < 4; q++) {
        part[q] += __shfl_xor_sync(0xffffffffu, part[q], 1);
        part[q] += __shfl_xor_sync(0xffffffffu, part[q], 2);
    }
    if (tg == 0) {
        const int r0 = warp_m * 32 + gq;
        sRD[warp_n * 64 + r0 +  0] = part[0];
        sRD[warp_n * 64 + r0 +  8] = part[1];
        sRD[warp_n * 64 + r0 + 16] = part[2];
        sRD[warp_n * 64 + r0 + 24] = part[3];
    }
    __syncthreads();

    if (tid < 64) {
        const int m = tid;
        const int k = kbase + m;
        const float s = sRD[m] + sRD[64 + m] + sRD[128 + m] + sRD[192 + m] + b3[0];
        if (k < WIN) {
            const int j = i - WIN + k;
            out[i * OUTW + k] = (j >= 0) ? (sm[i] + sm[j] + s) : 0.f;
        } else if (k == WIN) {
            out[i * OUTW + WIN] = 0.f;
        }
    }
}

// ---------------------------------------------------------------------------
extern "C" void kernel_launch(void* const* d_in, const int* in_sizes, int n_in,
                              void* d_out, int out_size) {
    const float* g  = (const float*)d_in[0];
    const float* sm = (const float*)d_in[1];
    const float* W1 = (const float*)d_in[2];
    const float* b1 = (const float*)d_in[3];
    const float* W2 = (const float*)d_in[4];
    const float* b2 = (const float*)d_in[5];
    const float* W3 = (const float*)d_in[6];
    const float* b3 = (const float*)d_in[7];
    float* out = (float*)d_out;

    cudaFuncSetAttribute(pair_mma_kernel, cudaFuncAttributeMaxDynamicSharedMemorySize,
                         SMEM_BYTES);

    proj_part_kernel<<<(N_SPANS / TI) * NDC, 160>>>(g, W1);
    prep_fused_kernel<<<N_SPANS + HP, 512>>>(g, W1, W2);
    proj_reduce_kernel<<<N_SPANS, 160>>>(b1);
    pair_mma_kernel<<<4 * N_SPANS, NT, SMEM_BYTES>>>(sm, W3, b2, b3, out);
}